// round 17
// baseline (speedup 1.0000x reference)
#include <cuda_runtime.h>
#include <cuda_bf16.h>

// pc:      (64, 1, 64, 128) float32 -> 524288 elems (131072 float4)
// targets: (64, 512, 1024)  int32   -> only [:64, :64, :] matters
//
// cond[y,x] = any(cell(y,x) elem == 2) && any(cell(y,x) elem != 2)
// loss = -mean( t*log(pc) + (1-t)*log(1-pc) ), t[b,y,x] = cond[y,x]·(y<8 && x<8)
//
// Round-15 vs round-14:
//   * 64 pc blocks x 32 elems/thread (8 float4, MLP 8, one DRAM round;
//     4 prod8 trees + 4 __logf, products >= 1e-32) -> 65 total atomics
//     (halves the same-address L2 atomic serialization burst again).
//   * flag block: ONE packed __reduce_or_sync for all 8 cells (2 bits each)
//     instead of 8 serial reductions (~210 cyc off the straggler).
//   * tail: lanes 0..7 redux the 8 warp sums (1 LDS + 1 redux vs 8 serial).
//   * fixed-point scale 2^14 (per-thread |acc| <= 295 -> block sum <= 1.24e9
//     < 2^31, int32 redux chain exact; quantization ~1e-6 rel).
// Packed 64-bit atomic tail (validated): bits 0..51 biased sum (+2^31/block),
// bits 52..63 arrival count; winner (count==NBLK-1) holds the full sum in
// (old+add), writes out, resets. Integer adds commute -> deterministic.
//   65 * (2^31 + 1.24e9) ~ 2^38 < 2^52 -> no carry into count field. OK

#define N_PC      524288
#define NBLK_PC   64
#define NBLK      65
#define FPSCALE   16384.0f            // 2^14 per-thread fixed-point scale
#define BLKBIAS   (1LL << 31)         // per-block bias (covers |block sum|)
#define TAG       (1ULL << 52)
#define MASK52    (TAG - 1ULL)

__device__ unsigned long long g_acc;  // zero-init at load; reset by winner

__device__ __forceinline__ float prod8_1m(const float4 a, const float4 b) {
    // prod of (1-x) over 8 lanes, depth-3 tree
    const float p0 = (1.0f - a.x) * (1.0f - a.y);
    const float p1 = (1.0f - a.z) * (1.0f - a.w);
    const float p2 = (1.0f - b.x) * (1.0f - b.y);
    const float p3 = (1.0f - b.z) * (1.0f - b.w);
    return (p0 * p1) * (p2 * p3);
}

__global__ void __launch_bounds__(256) fused_kernel(const int* __restrict__ targets,
                                                    const float* __restrict__ pc,
                                                    float* __restrict__ out) {
    const int blk  = blockIdx.x;
    const int tid  = threadIdx.x;
    const int lane = tid & 31;
    const int warp = tid >> 5;

    float acc = 0.0f;

    if (blk < NBLK_PC) {
        // ------------- pc blocks: 8 float4/thread, 4 product-logs --------------
        const float4* __restrict__ p4 =
            reinterpret_cast<const float4*>(pc) + blk * 2048 + tid;
        float4 v[8];
#pragma unroll
        for (int k = 0; k < 8; k++) v[k] = p4[k * 256];
        acc = __logf(prod8_1m(v[0], v[1])) + __logf(prod8_1m(v[2], v[3]))
            + __logf(prod8_1m(v[4], v[5])) + __logf(prod8_1m(v[6], v[7]));
    } else {
        // ------------- flag block: cond[64] + correction -----------------------
        // Specials: rows (b, y) with y<8, x in [0,8). 512 rows; thread t
        // handles rows 2t, 2t+1 (2 float4 each); loads issued FIRST.
        const int r0 = tid * 2;
        const int r1 = r0 + 1;
        const int b0 = r0 >> 3, y0 = r0 & 7;
        const int b1 = r1 >> 3, y1 = r1 & 7;
        const float4* __restrict__ p4 = reinterpret_cast<const float4*>(pc);
        const float4 pa0 = p4[b0 * 2048 + y0 * 32];
        const float4 pa1 = p4[b0 * 2048 + y0 * 32 + 1];
        const float4 pb0 = p4[b1 * 2048 + y1 * 32];
        const float4 pb1 = p4[b1 * 2048 + y1 * 32 + 1];

        // Warp w owns cells c = 8w..8w+8 (i = w, j = c&7). Round-0 of each cell
        // packed into one 16-bit word: cell q -> bits [2q, 2q+2).
        const int4* __restrict__ t4 = reinterpret_cast<const int4*>(targets);
        const size_t cell_base = (size_t)(8 * warp) * 131072 + lane;

        unsigned pk = 0;
#pragma unroll
        for (int q = 0; q < 8; q++) {
            const int4 t = t4[cell_base + (size_t)q * 8 * 256];
            const unsigned fb =
                  (((t.x == 2) | (t.y == 2) | (t.z == 2) | (t.w == 2)) ? 1u : 0u)
                | (((t.x != 2) | (t.y != 2) | (t.z != 2) | (t.w != 2)) ? 2u : 0u);
            pk |= fb << (2 * q);
        }
        pk = __reduce_or_sync(0xffffffffu, pk);   // ONE reduction for all 8 cells

        // Fallback full scan for undecided cells (~never on this distribution;
        // warp-uniform control flow, strictly bounded).
        if (pk != 0xFFFFu) {
#pragma unroll 1
            for (int q = 0; q < 8; q++) {
                if (((pk >> (2 * q)) & 3u) == 3u) continue;
                unsigned f = (pk >> (2 * q)) & 3u;
#pragma unroll 1
                for (int r = 1; r < 512; r++) {
                    const int bb = r >> 6, rem = r & 63;
                    const int rr = rem >> 3, ch = rem & 7;
                    const int4 t = t4[(size_t)(8 * warp + bb) * 131072
                                      + (size_t)(8 * q + rr) * 256 + ch * 32 + lane];
                    const unsigned fb =
                          (((t.x == 2) | (t.y == 2) | (t.z == 2) | (t.w == 2)) ? 1u : 0u)
                        | (((t.x != 2) | (t.y != 2) | (t.z != 2) | (t.w != 2)) ? 2u : 0u);
                    f = __reduce_or_sync(0xffffffffu, f | fb);
                    if (f == 3u) break;
                }
                pk |= f << (2 * q);
            }
        }

        __shared__ float s_cond[64];
        if (lane < 8)
            s_cond[warp * 8 + lane] = (((pk >> (2 * lane)) & 3u) == 3u) ? 1.0f : 0.0f;
        __syncthreads();

        // Correction per row: log(prod cond?p:1) - log(prod cond?(1-p):1).
        // Each product has 8 factors >= 1e-4 -> >= 1e-32, no underflow.
        const float* c0 = &s_cond[y0 * 8];
        const float* c1 = &s_cond[y1 * 8];
        {
            const float pv0[8] = {pa0.x, pa0.y, pa0.z, pa0.w,
                                  pa1.x, pa1.y, pa1.z, pa1.w};
            const float pv1[8] = {pb0.x, pb0.y, pb0.z, pb0.w,
                                  pb1.x, pb1.y, pb1.z, pb1.w};
            float n0 = 1.0f, d0 = 1.0f, n1 = 1.0f, d1 = 1.0f;
#pragma unroll
            for (int l = 0; l < 8; l++) {
                const bool t0 = c0[l] > 0.5f;
                const bool t1 = c1[l] > 0.5f;
                n0 *= t0 ? pv0[l]          : 1.0f;
                d0 *= t0 ? (1.0f - pv0[l]) : 1.0f;
                n1 *= t1 ? pv1[l]          : 1.0f;
                d1 *= t1 ? (1.0f - pv1[l]) : 1.0f;
            }
            acc = (__logf(n0) - __logf(d0)) + (__logf(n1) - __logf(d1));
        }
    }

    // ---------------- fixed-point block reduce ---------------------------------
    // scale 2^14: per-thread <= 295*2^14 = 4.8e6; warp <= 1.6e8; block <= 1.24e9
    // -> every int32 partial stays exact (no wrap anywhere).
    int iacc = __float2int_rn(acc * FPSCALE);
    iacc = (int)__reduce_add_sync(0xffffffffu, (unsigned)iacc);

    __shared__ int s_wi[8];
    if (lane == 0) s_wi[warp] = iacc;
    __syncthreads();

    // ---------------- single packed atomic: sum + arrival count ----------------
    if (warp == 0 && lane < 8) {
        const int bsum = (int)__reduce_add_sync(0xffu, (unsigned)s_wi[lane]);
        if (lane == 0) {
            const unsigned long long add =
                TAG + (unsigned long long)((long long)bsum + BLKBIAS);
            const unsigned long long old = atomicAdd(&g_acc, add);
            if ((old >> 52) == NBLK - 1) {
                // Last block: old+add holds ALL contributions (RMW atomicity).
                const long long total =
                    (long long)((old + add) & MASK52) - (long long)NBLK * BLKBIAS;
                const double sum = (double)total * (1.0 / 16384.0);
                g_acc = 0ULL;                   // reset for next graph replay
                *out = (float)(-sum * (1.0 / (double)N_PC));
            }
        }
    }
}

extern "C" void kernel_launch(void* const* d_in, const int* in_sizes, int n_in,
                              void* d_out, int out_size) {
    const float* pc;
    const int*   targets;
    if (in_sizes[0] == N_PC) {
        pc      = (const float*)d_in[0];
        targets = (const int*)d_in[1];
    } else {
        pc      = (const float*)d_in[1];
        targets = (const int*)d_in[0];
    }
    fused_kernel<<<NBLK, 256>>>(targets, pc, (float*)d_out);
}